// round 1
// baseline (speedup 1.0000x reference)
#include <cuda_runtime.h>
#include <cstdint>
#include <math.h>

// ---------------------------------------------------------------------------
// PFMLPScaledXY: out = L3( elu(L2( elu(L1(x)) )) )
//   Lk(inp) = p0*(inp@Wk0) + p1*(inp@Wk1) + p0*bk0 + p1*bk1,  p = x[:, 256:258]
// B=32768, D_IN=256, H=1024, D_OUT=64. MX/SX/MY/SY are identity.
//
// Strategy: one templated tf32 mma.sync GEMM kernel, 3 launches.
//   - A shared between modes; both mode-B tiles streamed per K-step.
//   - dual accumulators, per-row phase mix + bias + ELU fused in epilogue.
//   - cp.async double-buffered smem; fragments rounded to tf32 with cvt.rna
//     (RN needed: RZ truncation error ~1.05e-3 > 1e-3 threshold).
// ---------------------------------------------------------------------------

#define TBM 128
#define TBN 64
#define TBK 32
#define NTHREADS 256
// padded smem strides chosen for conflict-free fragment LDS:
//   A stride 36: bank = (4g + k) mod 32 over lane groups -> permutation
//   B stride 72: bank = (8t + g) mod 32 -> permutation
#define AS_STRIDE 36
#define BS_STRIDE 72
#define AS_ELEMS (TBM * AS_STRIDE)            // 4608 floats per buffer
#define BS_ELEMS (2 * TBK * BS_STRIDE)        // 4608 floats per buffer (2 modes)
#define SMEM_FLOATS (2 * AS_ELEMS + 2 * BS_ELEMS)
#define SMEM_BYTES (SMEM_FLOATS * 4)          // 73728 bytes

// scratch for hidden activations (allocation-free rule: __device__ globals)
__device__ float g_h1[32768ull * 1024];
__device__ float g_h2[32768ull * 1024];

__device__ __forceinline__ uint32_t f2tf32(float x) {
    uint32_t r;
    asm("cvt.rna.tf32.f32 %0, %1;" : "=r"(r) : "f"(x));
    return r;
}

__device__ __forceinline__ void mma_tf32(float* d, const uint32_t* a,
                                         uint32_t b0, uint32_t b1) {
    asm volatile(
        "mma.sync.aligned.m16n8k8.row.col.f32.tf32.tf32.f32 "
        "{%0,%1,%2,%3}, {%4,%5,%6,%7}, {%8,%9}, {%0,%1,%2,%3};"
        : "+f"(d[0]), "+f"(d[1]), "+f"(d[2]), "+f"(d[3])
        : "r"(a[0]), "r"(a[1]), "r"(a[2]), "r"(a[3]), "r"(b0), "r"(b1));
}

__device__ __forceinline__ uint32_t smem_addr_u32(const void* p) {
    return (uint32_t)__cvta_generic_to_shared(p);
}

__device__ __forceinline__ void cp_async8(uint32_t s, const void* g) {
    asm volatile("cp.async.ca.shared.global [%0], [%1], 8;" :: "r"(s), "l"(g));
}
__device__ __forceinline__ void cp_async16(uint32_t s, const void* g) {
    asm volatile("cp.async.ca.shared.global [%0], [%1], 16;" :: "r"(s), "l"(g));
}
__device__ __forceinline__ void cp_commit() {
    asm volatile("cp.async.commit_group;");
}
template <int N>
__device__ __forceinline__ void cp_wait() {
    asm volatile("cp.async.wait_group %0;" :: "n"(N));
}

// A: [M, K] row-major, leading dim lda (258 for x, 1024 for hidden)
// B0/B1: [K, N] row-major, leading dim ldb (= N)
// bias0/bias1: [N]
// xphase: x base pointer; phase at [r*258 + 256], [r*258 + 257]
// C: [M, N] row-major, leading dim ldc
template <bool DO_ELU>
__global__ void __launch_bounds__(NTHREADS) mode_gemm(
    const float* __restrict__ A, int lda, int K,
    const float* __restrict__ B0, const float* __restrict__ B1, int ldb,
    const float* __restrict__ bias0, const float* __restrict__ bias1,
    const float* __restrict__ xphase,
    float* __restrict__ C, int ldc)
{
    extern __shared__ float smem[];
    float* As0 = smem;
    float* As1 = smem + AS_ELEMS;
    float* Bsb = smem + 2 * AS_ELEMS;   // [buf][mode][TBK][BS_STRIDE]

    const int tid = threadIdx.x;
    const int wid = tid >> 5;
    const int lane = tid & 31;
    const int warp_m = wid & 3;     // 4 warps over M (32 rows each)
    const int warp_n = wid >> 2;    // 2 warps over N (32 cols each)
    const int g = lane >> 2;        // 0..7
    const int t = lane & 3;         // 0..3

    const int blockN = blockIdx.x * TBN;
    const long blockM = (long)blockIdx.y * TBM;

    float acc[2][2][4][4];          // [mode][mtile][ntile][frag]
    #pragma unroll
    for (int m = 0; m < 2; m++)
        #pragma unroll
        for (int i = 0; i < 2; i++)
            #pragma unroll
            for (int j = 0; j < 4; j++)
                #pragma unroll
                for (int q = 0; q < 4; q++)
                    acc[m][i][j][q] = 0.0f;

    const int nIter = K / TBK;

    // ---- async tile loader -------------------------------------------------
    auto issue_loads = [&](int it, int buf) {
        const int k0 = it * TBK;
        float* as = buf ? As1 : As0;
        // A tile: 128x32 = 2048 float2 chunks, 8 per thread (8B: x stride 258
        // rows are only 8B-aligned)
        #pragma unroll
        for (int c = 0; c < 8; c++) {
            int p = c * NTHREADS + tid;
            int row = p >> 4;
            int col2 = (p & 15) * 2;
            const float* gp = A + (blockM + row) * (long)lda + k0 + col2;
            cp_async8(smem_addr_u32(as + row * AS_STRIDE + col2), gp);
        }
        // B tiles: per mode 32x64 = 512 float4 chunks, 2 per thread
        #pragma unroll
        for (int m = 0; m < 2; m++) {
            const float* Bm = m ? B1 : B0;
            float* bs = Bsb + buf * BS_ELEMS + m * (TBK * BS_STRIDE);
            #pragma unroll
            for (int c = 0; c < 2; c++) {
                int p = c * NTHREADS + tid;
                int row = p >> 4;
                int col4 = (p & 15) * 4;
                const float* gp = Bm + (long)(k0 + row) * ldb + blockN + col4;
                cp_async16(smem_addr_u32(bs + row * BS_STRIDE + col4), gp);
            }
        }
        cp_commit();
    };

    issue_loads(0, 0);

    for (int it = 0; it < nIter; ++it) {
        const int buf = it & 1;
        if (it + 1 < nIter) {
            issue_loads(it + 1, buf ^ 1);
            cp_wait<1>();
        } else {
            cp_wait<0>();
        }
        __syncthreads();

        const float* as = buf ? As1 : As0;
        const float* bs0 = Bsb + buf * BS_ELEMS;
        const float* bs1 = bs0 + TBK * BS_STRIDE;

        #pragma unroll
        for (int kk = 0; kk < 4; kk++) {
            const int kidx = kk * 8 + t;
            uint32_t af[2][4];
            #pragma unroll
            for (int mt = 0; mt < 2; mt++) {
                const int rb = warp_m * 32 + mt * 16;
                af[mt][0] = f2tf32(as[(rb + g) * AS_STRIDE + kidx]);
                af[mt][1] = f2tf32(as[(rb + g + 8) * AS_STRIDE + kidx]);
                af[mt][2] = f2tf32(as[(rb + g) * AS_STRIDE + kidx + 4]);
                af[mt][3] = f2tf32(as[(rb + g + 8) * AS_STRIDE + kidx + 4]);
            }
            #pragma unroll
            for (int m = 0; m < 2; m++) {
                const float* bs = m ? bs1 : bs0;
                #pragma unroll
                for (int nt = 0; nt < 4; nt++) {
                    const int cb = warp_n * 32 + nt * 8;
                    uint32_t b0 = f2tf32(bs[kidx * BS_STRIDE + cb + g]);
                    uint32_t b1 = f2tf32(bs[(kidx + 4) * BS_STRIDE + cb + g]);
                    mma_tf32(acc[m][0][nt], af[0], b0, b1);
                    mma_tf32(acc[m][1][nt], af[1], b0, b1);
                }
            }
        }
        __syncthreads();
    }

    // ---- epilogue: per-row phase mix + bias + optional ELU ------------------
    #pragma unroll
    for (int mt = 0; mt < 2; mt++) {
        const long rbase = blockM + warp_m * 32 + mt * 16 + g;
        #pragma unroll
        for (int rr = 0; rr < 2; rr++) {
            const long r = rbase + rr * 8;
            const float p0 = __ldg(xphase + r * 258 + 256);
            const float p1 = __ldg(xphase + r * 258 + 257);
            #pragma unroll
            for (int nt = 0; nt < 4; nt++) {
                const int c = blockN + warp_n * 32 + nt * 8 + 2 * t;
                const float bb0 = p0 * __ldg(bias0 + c) + p1 * __ldg(bias1 + c);
                const float bb1 = p0 * __ldg(bias0 + c + 1) + p1 * __ldg(bias1 + c + 1);
                float v0 = p0 * acc[0][mt][nt][rr * 2 + 0]
                         + p1 * acc[1][mt][nt][rr * 2 + 0] + bb0;
                float v1 = p0 * acc[0][mt][nt][rr * 2 + 1]
                         + p1 * acc[1][mt][nt][rr * 2 + 1] + bb1;
                if (DO_ELU) {
                    v0 = v0 > 0.0f ? v0 : expm1f(v0);
                    v1 = v1 > 0.0f ? v1 : expm1f(v1);
                }
                float2 st = make_float2(v0, v1);
                *reinterpret_cast<float2*>(C + r * (long)ldc + c) = st;
            }
        }
    }
}

extern "C" void kernel_launch(void* const* d_in, const int* in_sizes, int n_in,
                              void* d_out, int out_size)
{
    const float* x  = (const float*)d_in[0];   // [B, 258]
    const float* w1 = (const float*)d_in[1];   // [2, 256, 1024]
    const float* b1 = (const float*)d_in[2];   // [2, 1024]
    const float* w2 = (const float*)d_in[3];   // [2, 1024, 1024]
    const float* b2 = (const float*)d_in[4];   // [2, 1024]
    const float* w3 = (const float*)d_in[5];   // [2, 1024, 64]
    const float* b3 = (const float*)d_in[6];   // [2, 64]
    float* out = (float*)d_out;

    const int DIN  = 256;
    const int H    = in_sizes[2] / 2;          // 1024
    const int DOUT = in_sizes[6] / 2;          // 64
    const int M    = in_sizes[0] / (DIN + 2);  // 32768

    float* h1p = nullptr;
    float* h2p = nullptr;
    cudaGetSymbolAddress((void**)&h1p, g_h1);
    cudaGetSymbolAddress((void**)&h2p, g_h2);

    cudaFuncSetAttribute((const void*)mode_gemm<true>,
                         cudaFuncAttributeMaxDynamicSharedMemorySize, SMEM_BYTES);
    cudaFuncSetAttribute((const void*)mode_gemm<false>,
                         cudaFuncAttributeMaxDynamicSharedMemorySize, SMEM_BYTES);

    dim3 blk(NTHREADS);
    dim3 grid1(H / TBN, M / TBM);      // (16, 256)
    dim3 grid3(DOUT / TBN, M / TBM);   // (1, 256)

    // Layer 1: x[:, :256] @ w1[mode] -> elu -> h1
    mode_gemm<true><<<grid1, blk, SMEM_BYTES>>>(
        x, DIN + 2, DIN, w1, w1 + (long)DIN * H, H,
        b1, b1 + H, x, h1p, H);

    // Layer 2: h1 @ w2[mode] -> elu -> h2
    mode_gemm<true><<<grid1, blk, SMEM_BYTES>>>(
        h1p, H, H, w2, w2 + (long)H * H, H,
        b2, b2 + H, x, h2p, H);

    // Layer 3: h2 @ w3[mode] -> out (linear)
    mode_gemm<false><<<grid3, blk, SMEM_BYTES>>>(
        h2p, H, H, w3, w3 + (long)H * DOUT, DOUT,
        b3, b3 + DOUT, x, out, DOUT);
}

// round 3
// speedup vs baseline: 2.5546x; 2.5546x over previous
#include <cuda_runtime.h>
#include <cuda_fp16.h>
#include <cstdint>
#include <math.h>

// ---------------------------------------------------------------------------
// PFMLPScaledXY via fp16 mma.sync.m16n8k16 (ptxas target lacks the 'a' suffix:
// tcgen05 is unavailable; legacy tensor pipe it is).
//   Lk(inp) = p0*(inp@Wk0) + p1*(inp@Wk1) + p0*bk0 + p1*bk1
// All operands pre-converted to half (RN) once; mainloop = cp.async double
// buffer -> SW128-swizzled smem -> ldmatrix.x4 -> HMMA, zero conversions.
// f32 accumulators; epilogue fuses phase-mix + bias + ELU, writes half h1/h2.
// ---------------------------------------------------------------------------

#define NTHREADS 256
#define TBM 128
#define TBN 64      // per mode
#define TBK 64

// scratch (__device__ globals: allocation-free rule)
__device__ __half g_xh [32768ull * 256];
__device__ __half g_w1h[2ull * 256 * 1024];
__device__ __half g_w2h[2ull * 1024 * 1024];
__device__ __half g_w3h[2ull * 1024 * 64];
__device__ __half g_h1 [32768ull * 1024];
__device__ __half g_h2 [32768ull * 1024];

// ---------------- PTX helpers ----------------------------------------------
__device__ __forceinline__ uint32_t smem_u32(const void* p) {
    return (uint32_t)__cvta_generic_to_shared(p);
}
__device__ __forceinline__ void cp_async16(uint32_t s, const void* g) {
    asm volatile("cp.async.ca.shared.global [%0], [%1], 16;" :: "r"(s), "l"(g));
}
__device__ __forceinline__ void cp_commit() {
    asm volatile("cp.async.commit_group;");
}
template <int N> __device__ __forceinline__ void cp_wait() {
    asm volatile("cp.async.wait_group %0;" :: "n"(N));
}
__device__ __forceinline__ void ldsm_x4(uint32_t* r, uint32_t a) {
    asm volatile("ldmatrix.sync.aligned.m8n8.x4.shared.b16 {%0,%1,%2,%3}, [%4];"
                 : "=r"(r[0]), "=r"(r[1]), "=r"(r[2]), "=r"(r[3]) : "r"(a));
}
__device__ __forceinline__ void ldsm_x4_t(uint32_t* r, uint32_t a) {
    asm volatile("ldmatrix.sync.aligned.m8n8.x4.trans.shared.b16 {%0,%1,%2,%3}, [%4];"
                 : "=r"(r[0]), "=r"(r[1]), "=r"(r[2]), "=r"(r[3]) : "r"(a));
}
__device__ __forceinline__ void mma_f16(float* d, const uint32_t* a,
                                        uint32_t b0, uint32_t b1) {
    asm volatile(
        "mma.sync.aligned.m16n8k16.row.col.f32.f16.f16.f32 "
        "{%0,%1,%2,%3}, {%4,%5,%6,%7}, {%8,%9}, {%0,%1,%2,%3};"
        : "+f"(d[0]), "+f"(d[1]), "+f"(d[2]), "+f"(d[3])
        : "r"(a[0]), "r"(a[1]), "r"(a[2]), "r"(a[3]), "r"(b0), "r"(b1));
}

// ---------------- preprocessing --------------------------------------------
// x [M,258] f32 -> xh [M,256] half
__global__ void conv_x_kernel(const float* __restrict__ x, __half* __restrict__ xh) {
    size_t idx = (size_t)blockIdx.x * blockDim.x + threadIdx.x;  // M*128 pairs
    size_t r = idx >> 7;
    int c = (int)(idx & 127) * 2;
    float2 v = *reinterpret_cast<const float2*>(x + r * 258 + c);
    *reinterpret_cast<__half2*>(xh + r * 256 + c) = __floats2half2_rn(v.x, v.y);
}
// generic f32 -> half, n float2 pairs
__global__ void conv_w_kernel(const float* __restrict__ w, __half* __restrict__ wh) {
    size_t idx = (size_t)blockIdx.x * blockDim.x + threadIdx.x;
    float2 v = reinterpret_cast<const float2*>(w)[idx];
    reinterpret_cast<__half2*>(wh)[idx] = __floats2half2_rn(v.x, v.y);
}

// ---------------- main GEMM ------------------------------------------------
// A [Mtot,K] half row-major (lda), B [2][K,ldb] half row-major (modeStride).
// Per CTA: rows blockM..+128, cols blockN..+64 (both modes).
// SMEM tile layout: 128-byte rows (64 halves), 16B chunk j at row m stored at
// chunk (j ^ (m&7)) -> conflict-free cp.async writes AND ldmatrix reads.
template <bool DO_ELU, bool OUT_HALF>
__global__ void __launch_bounds__(NTHREADS, 2) hgemm(
    const __half* __restrict__ A, int lda, int K,
    const __half* __restrict__ B, size_t modeStride, int ldb,
    const float* __restrict__ bias0, const float* __restrict__ bias1,
    const float* __restrict__ xphase,
    void* __restrict__ Cv, int ldc)
{
    constexpr int A_BYTES = TBM * 128;              // 16384
    constexpr int B_BYTES = TBK * 128;              // 8192 per mode
    constexpr int STAGE   = A_BYTES + 2 * B_BYTES;  // 32768

    extern __shared__ char smem[];
    const uint32_t sm = smem_u32(smem);

    const int tid  = threadIdx.x;
    const int wid  = tid >> 5;
    const int lane = tid & 31;
    const int warp_m = wid & 3;      // 4 warps over M (32 rows)
    const int warp_n = wid >> 2;     // 2 warps over N (32 cols)
    const size_t blockM = (size_t)blockIdx.y * TBM;
    const int blockN = blockIdx.x * TBN;

    float acc[2][2][4][4];           // [mode][mtile][ntile][frag]
    #pragma unroll
    for (int m = 0; m < 2; m++)
        #pragma unroll
        for (int i = 0; i < 2; i++)
            #pragma unroll
            for (int j = 0; j < 4; j++)
                #pragma unroll
                for (int q = 0; q < 4; q++) acc[m][i][j][q] = 0.0f;

    const int nk = K / TBK;

    auto load_stage = [&](int kt, int buf) {
        const int k0 = kt * TBK;
        const uint32_t st = sm + buf * STAGE;
        // A: 128 rows x 8 chunks = 1024 chunks, 4/thread
        #pragma unroll
        for (int c = 0; c < 4; c++) {
            int p = c * NTHREADS + tid;
            int row = p >> 3, j = p & 7;
            uint32_t dst = st + row * 128 + ((j ^ (row & 7)) << 4);
            cp_async16(dst, A + (blockM + row) * (size_t)lda + k0 + j * 8);
        }
        // B: per mode 64 rows x 8 chunks = 512 chunks, 2/thread
        #pragma unroll
        for (int m = 0; m < 2; m++) {
            const __half* Bm = B + m * modeStride;
            const uint32_t bst = st + A_BYTES + m * B_BYTES;
            #pragma unroll
            for (int c = 0; c < 2; c++) {
                int p = c * NTHREADS + tid;
                int row = p >> 3, j = p & 7;
                uint32_t dst = bst + row * 128 + ((j ^ (row & 7)) << 4);
                cp_async16(dst, Bm + (size_t)(k0 + row) * ldb + blockN + j * 8);
            }
        }
        cp_commit();
    };

    load_stage(0, 0);
    load_stage(1, 1);

    for (int i = 0; i < nk; i++) {
        const int buf = i & 1;
        if (i == nk - 1) cp_wait<0>(); else cp_wait<1>();
        __syncthreads();

        const uint32_t st = sm + buf * STAGE;
        #pragma unroll
        for (int kk = 0; kk < 4; kk++) {
            // A fragments: lanes 0-7 rows+0 j0 | 8-15 rows+8 j0 | 16-23 rows+0 j1 | 24-31 rows+8 j1
            uint32_t a[2][4];
            const int jA = kk * 2 + (lane >> 4);
            #pragma unroll
            for (int mt = 0; mt < 2; mt++) {
                const int m = warp_m * 32 + mt * 16 + (lane & 15);
                ldsm_x4(a[mt], st + m * 128 + ((jA ^ (m & 7)) << 4));
            }
            // B fragments (trans): lanes 0-7 k+0 jn | 8-15 k+8 jn | 16-31 jn+1
            const int krow = kk * 16 + (lane & 15);
            #pragma unroll
            for (int m = 0; m < 2; m++) {
                const uint32_t bst = st + A_BYTES + m * B_BYTES;
                #pragma unroll
                for (int ntg = 0; ntg < 2; ntg++) {
                    const int jn = warp_n * 4 + ntg * 2 + (lane >> 4);
                    uint32_t b[4];
                    ldsm_x4_t(b, bst + krow * 128 + ((jn ^ (krow & 7)) << 4));
                    mma_f16(acc[m][0][ntg * 2 + 0], a[0], b[0], b[1]);
                    mma_f16(acc[m][0][ntg * 2 + 1], a[0], b[2], b[3]);
                    mma_f16(acc[m][1][ntg * 2 + 0], a[1], b[0], b[1]);
                    mma_f16(acc[m][1][ntg * 2 + 1], a[1], b[2], b[3]);
                }
            }
        }
        __syncthreads();
        if (i + 2 < nk) load_stage(i + 2, buf);
    }

    // ---- epilogue: phase mix + bias + ELU ----------------------------------
    #pragma unroll
    for (int mt = 0; mt < 2; mt++) {
        #pragma unroll
        for (int rr = 0; rr < 2; rr++) {
            const size_t r = blockM + warp_m * 32 + mt * 16 + rr * 8 + (lane >> 2);
            const float p0 = __ldg(xphase + r * 258 + 256);
            const float p1 = __ldg(xphase + r * 258 + 257);
            #pragma unroll
            for (int nt = 0; nt < 4; nt++) {
                const int col = blockN + warp_n * 32 + nt * 8 + (lane & 3) * 2;
                float v0 = p0 * acc[0][mt][nt][rr * 2 + 0]
                         + p1 * acc[1][mt][nt][rr * 2 + 0]
                         + p0 * __ldg(bias0 + col) + p1 * __ldg(bias1 + col);
                float v1 = p0 * acc[0][mt][nt][rr * 2 + 1]
                         + p1 * acc[1][mt][nt][rr * 2 + 1]
                         + p0 * __ldg(bias0 + col + 1) + p1 * __ldg(bias1 + col + 1);
                if (DO_ELU) {
                    v0 = v0 > 0.0f ? v0 : expm1f(v0);
                    v1 = v1 > 0.0f ? v1 : expm1f(v1);
                }
                if (OUT_HALF) {
                    __half* C = (__half*)Cv;
                    *reinterpret_cast<__half2*>(C + r * ldc + col) =
                        __floats2half2_rn(v0, v1);
                } else {
                    float* C = (float*)Cv;
                    *reinterpret_cast<float2*>(C + r * ldc + col) =
                        make_float2(v0, v1);
                }
            }
        }
    }
}

// ---------------------------------------------------------------------------
extern "C" void kernel_launch(void* const* d_in, const int* in_sizes, int n_in,
                              void* d_out, int out_size)
{
    const float* x  = (const float*)d_in[0];   // [B, 258]
    const float* w1 = (const float*)d_in[1];   // [2, 256, 1024]
    const float* b1 = (const float*)d_in[2];
    const float* w2 = (const float*)d_in[3];   // [2, 1024, 1024]
    const float* b2 = (const float*)d_in[4];
    const float* w3 = (const float*)d_in[5];   // [2, 1024, 64]
    const float* b3 = (const float*)d_in[6];
    float* out = (float*)d_out;

    const int M = 32768, DIN = 256, H = 1024, DOUT = 64;

    __half *xh, *w1h, *w2h, *w3h, *h1, *h2;
    cudaGetSymbolAddress((void**)&xh,  g_xh);
    cudaGetSymbolAddress((void**)&w1h, g_w1h);
    cudaGetSymbolAddress((void**)&w2h, g_w2h);
    cudaGetSymbolAddress((void**)&w3h, g_w3h);
    cudaGetSymbolAddress((void**)&h1,  g_h1);
    cudaGetSymbolAddress((void**)&h2,  g_h2);

    const int SMEM = 2 * (128 * 128 + 2 * 64 * 128);   // 65536
    cudaFuncSetAttribute((const void*)hgemm<true, true>,
                         cudaFuncAttributeMaxDynamicSharedMemorySize, SMEM);
    cudaFuncSetAttribute((const void*)hgemm<false, false>,
                         cudaFuncAttributeMaxDynamicSharedMemorySize, SMEM);

    // preprocess: convert to half once
    conv_x_kernel<<<M * 128 / 256, 256>>>(x, xh);
    conv_w_kernel<<<2 * DIN * H / 2 / 256, 256>>>(w1, w1h);
    conv_w_kernel<<<2 * H * H / 2 / 256, 256>>>(w2, w2h);
    conv_w_kernel<<<2 * H * DOUT / 2 / 256, 256>>>(w3, w3h);

    dim3 blk(NTHREADS);
    // L1: xh[32768,256] @ w1 -> elu -> h1 (half)
    hgemm<true, true><<<dim3(H / TBN, M / TBM), blk, SMEM>>>(
        xh, DIN, DIN, w1h, (size_t)DIN * H, H, b1, b1 + H, x, h1, H);
    // L2: h1 @ w2 -> elu -> h2 (half)
    hgemm<true, true><<<dim3(H / TBN, M / TBM), blk, SMEM>>>(
        h1, H, H, w2h, (size_t)H * H, H, b2, b2 + H, x, h2, H);
    // L3: h2 @ w3 -> out (f32)
    hgemm<false, false><<<dim3(DOUT / TBN, M / TBM), blk, SMEM>>>(
        h2, H, H, w3h, (size_t)H * DOUT, DOUT, b3, b3 + DOUT, x, out, DOUT);
}

// round 4
// speedup vs baseline: 3.1563x; 1.2355x over previous
#include <cuda_runtime.h>
#include <cuda_fp16.h>
#include <cstdint>
#include <math.h>

// ---------------------------------------------------------------------------
// PFMLPScaledXY via fp16 mma.sync.m16n8k16 (ptxas target = plain sm_100:
// tcgen05 unavailable -> legacy tensor pipe).
//   Lk(inp) = p0*(inp@Wk0) + p1*(inp@Wk1) + p0*bk0 + p1*bk1
// R4 changes vs R3 (612us):
//   - 3-stage circular cp.async pipeline, ONE __syncthreads per K-tile,
//     2 groups in flight during compute (was: 2 syncs, 1 group).
//   - K as template param: fully unrolled mainloop, constant buffer offsets.
//   - cp.async.cg (L2-only) for streaming tiles.
//   - weight conversions merged into one launch.
// ---------------------------------------------------------------------------

#define NTHREADS 256
#define TBM 128
#define TBN 64      // per mode
#define TBK 64

// scratch (__device__ globals: allocation-free rule)
__device__ __half g_xh [32768ull * 256];
__device__ __half g_w1h[2ull * 256 * 1024];
__device__ __half g_w2h[2ull * 1024 * 1024];
__device__ __half g_w3h[2ull * 1024 * 64];
__device__ __half g_h1 [32768ull * 1024];
__device__ __half g_h2 [32768ull * 1024];

// ---------------- PTX helpers ----------------------------------------------
__device__ __forceinline__ uint32_t smem_u32(const void* p) {
    return (uint32_t)__cvta_generic_to_shared(p);
}
__device__ __forceinline__ void cp_async16(uint32_t s, const void* g) {
    asm volatile("cp.async.cg.shared.global [%0], [%1], 16;" :: "r"(s), "l"(g));
}
__device__ __forceinline__ void cp_commit() {
    asm volatile("cp.async.commit_group;");
}
template <int N> __device__ __forceinline__ void cp_wait() {
    asm volatile("cp.async.wait_group %0;" :: "n"(N));
}
__device__ __forceinline__ void ldsm_x4(uint32_t* r, uint32_t a) {
    asm volatile("ldmatrix.sync.aligned.m8n8.x4.shared.b16 {%0,%1,%2,%3}, [%4];"
                 : "=r"(r[0]), "=r"(r[1]), "=r"(r[2]), "=r"(r[3]) : "r"(a));
}
__device__ __forceinline__ void ldsm_x4_t(uint32_t* r, uint32_t a) {
    asm volatile("ldmatrix.sync.aligned.m8n8.x4.trans.shared.b16 {%0,%1,%2,%3}, [%4];"
                 : "=r"(r[0]), "=r"(r[1]), "=r"(r[2]), "=r"(r[3]) : "r"(a));
}
__device__ __forceinline__ void mma_f16(float* d, const uint32_t* a,
                                        uint32_t b0, uint32_t b1) {
    asm volatile(
        "mma.sync.aligned.m16n8k16.row.col.f32.f16.f16.f32 "
        "{%0,%1,%2,%3}, {%4,%5,%6,%7}, {%8,%9}, {%0,%1,%2,%3};"
        : "+f"(d[0]), "+f"(d[1]), "+f"(d[2]), "+f"(d[3])
        : "r"(a[0]), "r"(a[1]), "r"(a[2]), "r"(a[3]), "r"(b0), "r"(b1));
}

// ---------------- preprocessing --------------------------------------------
// x [M,258] f32 -> xh [M,256] half
__global__ void conv_x_kernel(const float* __restrict__ x, __half* __restrict__ xh) {
    size_t idx = (size_t)blockIdx.x * blockDim.x + threadIdx.x;  // M*128 pairs
    size_t r = idx >> 7;
    int c = (int)(idx & 127) * 2;
    float2 v = *reinterpret_cast<const float2*>(x + r * 258 + c);
    *reinterpret_cast<__half2*>(xh + r * 256 + c) = __floats2half2_rn(v.x, v.y);
}
// all three weight tensors in one launch; sizes in float2 pairs
__global__ void conv_w3_kernel(const float* __restrict__ w1, __half* __restrict__ w1h,
                               const float* __restrict__ w2, __half* __restrict__ w2h,
                               const float* __restrict__ w3, __half* __restrict__ w3h,
                               int n1, int n2, int n3) {
    int idx = blockIdx.x * blockDim.x + threadIdx.x;
    const float* src; __half* dst; int i;
    if (idx < n1)                { src = w1; dst = w1h; i = idx; }
    else if (idx < n1 + n2)      { src = w2; dst = w2h; i = idx - n1; }
    else if (idx < n1 + n2 + n3) { src = w3; dst = w3h; i = idx - n1 - n2; }
    else return;
    float2 v = reinterpret_cast<const float2*>(src)[i];
    reinterpret_cast<__half2*>(dst)[i] = __floats2half2_rn(v.x, v.y);
}

// ---------------- main GEMM ------------------------------------------------
// A [Mtot,K] half row-major (lda == K), B [2][K,ldb] half row-major.
// Per CTA: rows blockM..+128, cols blockN..+64 (both modes).
// SMEM tile layout: 128-byte rows (64 halves); 16B chunk j of row m stored at
// chunk (j ^ (m&7)) -> conflict-free for cp.async writes AND ldmatrix reads.
template <int K, bool DO_ELU, bool OUT_HALF>
__global__ void __launch_bounds__(NTHREADS, 2) hgemm(
    const __half* __restrict__ A,
    const __half* __restrict__ B, size_t modeStride, int ldb,
    const float* __restrict__ bias0, const float* __restrict__ bias1,
    const float* __restrict__ xphase,
    void* __restrict__ Cv, int ldc)
{
    constexpr int A_BYTES = TBM * 128;              // 16384
    constexpr int B_BYTES = TBK * 128;              // 8192 per mode
    constexpr int STAGE   = A_BYTES + 2 * B_BYTES;  // 32768
    constexpr int NK      = K / TBK;

    extern __shared__ char smem[];
    const uint32_t sm = smem_u32(smem);

    const int tid  = threadIdx.x;
    const int wid  = tid >> 5;
    const int lane = tid & 31;
    const int warp_m = wid & 3;      // 4 warps over M (32 rows)
    const int warp_n = wid >> 2;     // 2 warps over N (32 cols)
    const size_t blockM = (size_t)blockIdx.y * TBM;
    const int blockN = blockIdx.x * TBN;

    float acc[2][2][4][4];           // [mode][mtile][ntile][frag]
    #pragma unroll
    for (int m = 0; m < 2; m++)
        #pragma unroll
        for (int i = 0; i < 2; i++)
            #pragma unroll
            for (int j = 0; j < 4; j++)
                #pragma unroll
                for (int q = 0; q < 4; q++) acc[m][i][j][q] = 0.0f;

    auto load_stage = [&](int kt, int buf) {
        const int k0 = kt * TBK;
        const uint32_t st = sm + buf * STAGE;
        // A: 128 rows x 8 chunks = 1024 chunks, 4/thread
        #pragma unroll
        for (int c = 0; c < 4; c++) {
            int p = c * NTHREADS + tid;
            int row = p >> 3, j = p & 7;
            uint32_t dst = st + row * 128 + ((j ^ (row & 7)) << 4);
            cp_async16(dst, A + (blockM + row) * (size_t)K + k0 + j * 8);
        }
        // B: per mode 64 rows x 8 chunks = 512 chunks, 2/thread
        #pragma unroll
        for (int m = 0; m < 2; m++) {
            const __half* Bm = B + m * modeStride;
            const uint32_t bst = st + A_BYTES + m * B_BYTES;
            #pragma unroll
            for (int c = 0; c < 2; c++) {
                int p = c * NTHREADS + tid;
                int row = p >> 3, j = p & 7;
                uint32_t dst = bst + row * 128 + ((j ^ (row & 7)) << 4);
                cp_async16(dst, Bm + (size_t)(k0 + row) * ldb + blockN + j * 8);
            }
        }
        cp_commit();
    };

    // 3-stage circular pipeline, loads 2 ahead, ONE barrier per iteration.
    load_stage(0, 0);
    load_stage(1, 1);

    #pragma unroll
    for (int i = 0; i < NK; i++) {
        if (i == NK - 1) cp_wait<0>(); else cp_wait<1>();
        __syncthreads();                       // all warps done with buf (i-1)%3
        if (i + 2 < NK) load_stage(i + 2, (i + 2) % 3);

        const uint32_t st = sm + (i % 3) * STAGE;
        #pragma unroll
        for (int kk = 0; kk < 4; kk++) {
            uint32_t a[2][4];
            const int jA = kk * 2 + (lane >> 4);
            #pragma unroll
            for (int mt = 0; mt < 2; mt++) {
                const int m = warp_m * 32 + mt * 16 + (lane & 15);
                ldsm_x4(a[mt], st + m * 128 + ((jA ^ (m & 7)) << 4));
            }
            const int krow = kk * 16 + (lane & 15);
            #pragma unroll
            for (int m = 0; m < 2; m++) {
                const uint32_t bst = st + A_BYTES + m * B_BYTES;
                #pragma unroll
                for (int ntg = 0; ntg < 2; ntg++) {
                    const int jn = warp_n * 4 + ntg * 2 + (lane >> 4);
                    uint32_t b[4];
                    ldsm_x4_t(b, bst + krow * 128 + ((jn ^ (krow & 7)) << 4));
                    mma_f16(acc[m][0][ntg * 2 + 0], a[0], b[0], b[1]);
                    mma_f16(acc[m][0][ntg * 2 + 1], a[0], b[2], b[3]);
                    mma_f16(acc[m][1][ntg * 2 + 0], a[1], b[0], b[1]);
                    mma_f16(acc[m][1][ntg * 2 + 1], a[1], b[2], b[3]);
                }
            }
        }
    }

    // ---- epilogue: phase mix + bias + ELU ----------------------------------
    #pragma unroll
    for (int mt = 0; mt < 2; mt++) {
        #pragma unroll
        for (int rr = 0; rr < 2; rr++) {
            const size_t r = blockM + warp_m * 32 + mt * 16 + rr * 8 + (lane >> 2);
            const float p0 = __ldg(xphase + r * 258 + 256);
            const float p1 = __ldg(xphase + r * 258 + 257);
            #pragma unroll
            for (int nt = 0; nt < 4; nt++) {
                const int col = blockN + warp_n * 32 + nt * 8 + (lane & 3) * 2;
                float v0 = p0 * acc[0][mt][nt][rr * 2 + 0]
                         + p1 * acc[1][mt][nt][rr * 2 + 0]
                         + p0 * __ldg(bias0 + col) + p1 * __ldg(bias1 + col);
                float v1 = p0 * acc[0][mt][nt][rr * 2 + 1]
                         + p1 * acc[1][mt][nt][rr * 2 + 1]
                         + p0 * __ldg(bias0 + col + 1) + p1 * __ldg(bias1 + col + 1);
                if (DO_ELU) {
                    v0 = v0 > 0.0f ? v0 : expm1f(v0);
                    v1 = v1 > 0.0f ? v1 : expm1f(v1);
                }
                if (OUT_HALF) {
                    __half* C = (__half*)Cv;
                    *reinterpret_cast<__half2*>(C + r * ldc + col) =
                        __floats2half2_rn(v0, v1);
                } else {
                    float* C = (float*)Cv;
                    *reinterpret_cast<float2*>(C + r * ldc + col) =
                        make_float2(v0, v1);
                }
            }
        }
    }
}

// ---------------------------------------------------------------------------
extern "C" void kernel_launch(void* const* d_in, const int* in_sizes, int n_in,
                              void* d_out, int out_size)
{
    const float* x  = (const float*)d_in[0];   // [B, 258]
    const float* w1 = (const float*)d_in[1];   // [2, 256, 1024]
    const float* b1 = (const float*)d_in[2];
    const float* w2 = (const float*)d_in[3];   // [2, 1024, 1024]
    const float* b2 = (const float*)d_in[4];
    const float* w3 = (const float*)d_in[5];   // [2, 1024, 64]
    const float* b3 = (const float*)d_in[6];
    float* out = (float*)d_out;

    const int M = 32768, DIN = 256, H = 1024, DOUT = 64;

    __half *xh, *w1h, *w2h, *w3h, *h1, *h2;
    cudaGetSymbolAddress((void**)&xh,  g_xh);
    cudaGetSymbolAddress((void**)&w1h, g_w1h);
    cudaGetSymbolAddress((void**)&w2h, g_w2h);
    cudaGetSymbolAddress((void**)&w3h, g_w3h);
    cudaGetSymbolAddress((void**)&h1,  g_h1);
    cudaGetSymbolAddress((void**)&h2,  g_h2);

    const int SMEM = 3 * (128 * 128 + 2 * 64 * 128);   // 98304 (3 stages)
    cudaFuncSetAttribute((const void*)hgemm<256, true, true>,
                         cudaFuncAttributeMaxDynamicSharedMemorySize, SMEM);
    cudaFuncSetAttribute((const void*)hgemm<1024, true, true>,
                         cudaFuncAttributeMaxDynamicSharedMemorySize, SMEM);
    cudaFuncSetAttribute((const void*)hgemm<1024, false, false>,
                         cudaFuncAttributeMaxDynamicSharedMemorySize, SMEM);

    // preprocess: convert to half once (2 launches)
    conv_x_kernel<<<M * 128 / 256, 256>>>(x, xh);
    {
        int n1 = 2 * DIN * H / 2, n2 = 2 * H * H / 2, n3 = 2 * H * DOUT / 2;
        conv_w3_kernel<<<(n1 + n2 + n3 + 255) / 256, 256>>>(
            w1, w1h, w2, w2h, w3, w3h, n1, n2, n3);
    }

    dim3 blk(NTHREADS);
    // L1: xh[32768,256] @ w1 -> elu -> h1 (half)
    hgemm<256, true, true><<<dim3(H / TBN, M / TBM), blk, SMEM>>>(
        xh, w1h, (size_t)DIN * H, H, b1, b1 + H, x, h1, H);
    // L2: h1 @ w2 -> elu -> h2 (half)
    hgemm<1024, true, true><<<dim3(H / TBN, M / TBM), blk, SMEM>>>(
        h1, w2h, (size_t)H * H, H, b2, b2 + H, x, h2, H);
    // L3: h2 @ w3 -> out (f32)
    hgemm<1024, false, false><<<dim3(DOUT / TBN, M / TBM), blk, SMEM>>>(
        h2, w3h, (size_t)H * DOUT, DOUT, b3, b3 + DOUT, x, out, DOUT);
}

// round 6
// speedup vs baseline: 3.1826x; 1.0083x over previous
#include <cuda_runtime.h>
#include <cuda_fp16.h>
#include <cstdint>
#include <math.h>

// ---------------------------------------------------------------------------
// PFMLPScaledXY via fp16 mma.sync.m16n8k16 (ptxas target = plain sm_100:
// tcgen05 unavailable -> legacy tensor pipe).
//   Lk(inp) = p0*(inp@Wk0) + p1*(inp@Wk1) + p0*bk0 + p1*bk1
// R6 = R5 (register double-buffered fragments) with the conv_x alignment bug
// fixed: x rows stride 258 floats = 1032B (8 mod 16) -> float4 loads trap;
// use float2.
// ---------------------------------------------------------------------------

#define NTHREADS 256
#define TBM 128
#define TBN 64      // per mode
#define TBK 64

// scratch (__device__ globals: allocation-free rule)
__device__ __half g_xh [32768ull * 256];
__device__ __half g_w1h[2ull * 256 * 1024];
__device__ __half g_w2h[2ull * 1024 * 1024];
__device__ __half g_w3h[2ull * 1024 * 64];
__device__ __half g_h1 [32768ull * 1024];
__device__ __half g_h2 [32768ull * 1024];

// ---------------- PTX helpers ----------------------------------------------
__device__ __forceinline__ uint32_t smem_u32(const void* p) {
    return (uint32_t)__cvta_generic_to_shared(p);
}
__device__ __forceinline__ void cp_async16(uint32_t s, const void* g) {
    asm volatile("cp.async.cg.shared.global [%0], [%1], 16;" :: "r"(s), "l"(g));
}
__device__ __forceinline__ void cp_commit() {
    asm volatile("cp.async.commit_group;");
}
template <int N> __device__ __forceinline__ void cp_wait() {
    asm volatile("cp.async.wait_group %0;" :: "n"(N));
}
__device__ __forceinline__ void ldsm_x4(uint32_t* r, uint32_t a) {
    asm volatile("ldmatrix.sync.aligned.m8n8.x4.shared.b16 {%0,%1,%2,%3}, [%4];"
                 : "=r"(r[0]), "=r"(r[1]), "=r"(r[2]), "=r"(r[3]) : "r"(a));
}
__device__ __forceinline__ void ldsm_x4_t(uint32_t* r, uint32_t a) {
    asm volatile("ldmatrix.sync.aligned.m8n8.x4.trans.shared.b16 {%0,%1,%2,%3}, [%4];"
                 : "=r"(r[0]), "=r"(r[1]), "=r"(r[2]), "=r"(r[3]) : "r"(a));
}
__device__ __forceinline__ void mma_f16(float* d, const uint32_t* a,
                                        uint32_t b0, uint32_t b1) {
    asm volatile(
        "mma.sync.aligned.m16n8k16.row.col.f32.f16.f16.f32 "
        "{%0,%1,%2,%3}, {%4,%5,%6,%7}, {%8,%9}, {%0,%1,%2,%3};"
        : "+f"(d[0]), "+f"(d[1]), "+f"(d[2]), "+f"(d[3])
        : "r"(a[0]), "r"(a[1]), "r"(a[2]), "r"(a[3]), "r"(b0), "r"(b1));
}

// ---------------- preprocessing --------------------------------------------
// x [M,258] f32 -> xh [M,256] half. float2 loads only: row stride 1032B is
// 8-byte aligned, NOT 16.
__global__ void conv_x_kernel(const float* __restrict__ x, __half* __restrict__ xh) {
    size_t idx = (size_t)blockIdx.x * blockDim.x + threadIdx.x;  // M*128 pairs
    size_t r = idx >> 7;
    int c = (int)(idx & 127) * 2;
    float2 v = *reinterpret_cast<const float2*>(x + r * 258 + c);
    *reinterpret_cast<__half2*>(xh + r * 256 + c) = __floats2half2_rn(v.x, v.y);
}
// all three weight tensors in one launch; sizes in float4 quads (contiguous,
// 16B-aligned bases -> float4 OK here)
__global__ void conv_w3_kernel(const float* __restrict__ w1, __half* __restrict__ w1h,
                               const float* __restrict__ w2, __half* __restrict__ w2h,
                               const float* __restrict__ w3, __half* __restrict__ w3h,
                               int n1, int n2, int n3) {
    int idx = blockIdx.x * blockDim.x + threadIdx.x;
    const float* src; __half* dst; int i;
    if (idx < n1)                { src = w1; dst = w1h; i = idx; }
    else if (idx < n1 + n2)      { src = w2; dst = w2h; i = idx - n1; }
    else if (idx < n1 + n2 + n3) { src = w3; dst = w3h; i = idx - n1 - n2; }
    else return;
    float4 v = reinterpret_cast<const float4*>(src)[i];
    __half2 h0 = __floats2half2_rn(v.x, v.y);
    __half2 h1 = __floats2half2_rn(v.z, v.w);
    reinterpret_cast<__half2*>(dst)[i * 2]     = h0;
    reinterpret_cast<__half2*>(dst)[i * 2 + 1] = h1;
}

// ---------------- main GEMM ------------------------------------------------
// A [Mtot,K] half row-major (lda == K), B [2][K,ldb] half row-major.
// Per CTA: rows blockM..+128, cols blockN..+64 (both modes).
// SMEM tile: 128-byte rows (64 halves); 16B chunk j of row m stored at chunk
// (j ^ (m&7)) -> conflict-free for cp.async writes AND ldmatrix reads.
template <int K, bool DO_ELU, bool OUT_HALF>
__global__ void __launch_bounds__(NTHREADS, 2) hgemm(
    const __half* __restrict__ A,
    const __half* __restrict__ B, size_t modeStride, int ldb,
    const float* __restrict__ bias0, const float* __restrict__ bias1,
    const float* __restrict__ xphase,
    void* __restrict__ Cv, int ldc)
{
    constexpr int A_BYTES = TBM * 128;              // 16384
    constexpr int B_BYTES = TBK * 128;              // 8192 per mode
    constexpr int STAGE   = A_BYTES + 2 * B_BYTES;  // 32768
    constexpr int NK      = K / TBK;

    extern __shared__ char smem[];
    const uint32_t sm = smem_u32(smem);

    const int tid  = threadIdx.x;
    const int wid  = tid >> 5;
    const int lane = tid & 31;
    const int warp_m = wid & 3;      // 4 warps over M (32 rows)
    const int warp_n = wid >> 2;     // 2 warps over N (32 cols)
    const size_t blockM = (size_t)blockIdx.y * TBM;
    const int blockN = blockIdx.x * TBN;

    float acc[2][2][4][4];           // [mode][mtile][ntile][frag]
    #pragma unroll
    for (int m = 0; m < 2; m++)
        #pragma unroll
        for (int i = 0; i < 2; i++)
            #pragma unroll
            for (int j = 0; j < 4; j++)
                #pragma unroll
                for (int q = 0; q < 4; q++) acc[m][i][j][q] = 0.0f;

    auto load_stage = [&](int kt, int buf) {
        const int k0 = kt * TBK;
        const uint32_t st = sm + buf * STAGE;
        // A: 128 rows x 8 chunks = 1024 chunks, 4/thread
        #pragma unroll
        for (int c = 0; c < 4; c++) {
            int p = c * NTHREADS + tid;
            int row = p >> 3, j = p & 7;
            uint32_t dst = st + row * 128 + ((j ^ (row & 7)) << 4);
            cp_async16(dst, A + (blockM + row) * (size_t)K + k0 + j * 8);
        }
        // B: per mode 64 rows x 8 chunks = 512 chunks, 2/thread
        #pragma unroll
        for (int m = 0; m < 2; m++) {
            const __half* Bm = B + m * modeStride;
            const uint32_t bst = st + A_BYTES + m * B_BYTES;
            #pragma unroll
            for (int c = 0; c < 2; c++) {
                int p = c * NTHREADS + tid;
                int row = p >> 3, j = p & 7;
                uint32_t dst = bst + row * 128 + ((j ^ (row & 7)) << 4);
                cp_async16(dst, Bm + (size_t)(k0 + row) * ldb + blockN + j * 8);
            }
        }
        cp_commit();
    };

    // fragment loader for one kk step (K=16 slice) of stage st
    auto ld_frags = [&](uint32_t st, int kk, uint32_t a[2][4], uint32_t b[2][2][4]) {
        const int jA = kk * 2 + (lane >> 4);
        #pragma unroll
        for (int mt = 0; mt < 2; mt++) {
            const int m = warp_m * 32 + mt * 16 + (lane & 15);
            ldsm_x4(a[mt], st + m * 128 + ((jA ^ (m & 7)) << 4));
        }
        const int krow = kk * 16 + (lane & 15);
        #pragma unroll
        for (int m = 0; m < 2; m++) {
            const uint32_t bst = st + A_BYTES + m * B_BYTES;
            #pragma unroll
            for (int ntg = 0; ntg < 2; ntg++) {
                const int jn = warp_n * 4 + ntg * 2 + (lane >> 4);
                ldsm_x4_t(b[m][ntg], bst + krow * 128 + ((jn ^ (krow & 7)) << 4));
            }
        }
    };

    // 3-stage circular smem pipeline + 2-deep register fragment pipeline.
    load_stage(0, 0);
    load_stage(1, 1);

    uint32_t afr[2][2][4];       // [buf][mtile][4]
    uint32_t bfr[2][2][2][4];    // [buf][mode][ntg][4]

    #pragma unroll
    for (int i = 0; i < NK; i++) {
        if (i == NK - 1) cp_wait<0>(); else cp_wait<1>();
        __syncthreads();                       // all warps done with buf (i-1)%3
        const uint32_t st = sm + (i % 3) * STAGE;

        // kk=0 fragments first; next-stage cp.async issue fills their latency
        ld_frags(st, 0, afr[0], bfr[0]);
        if (i + 2 < NK) load_stage(i + 2, (i + 2) % 3);

        #pragma unroll
        for (int kk = 0; kk < 4; kk++) {
            const int cur = kk & 1, nxt = cur ^ 1;
            if (kk < 3) ld_frags(st, kk + 1, afr[nxt], bfr[nxt]);
            #pragma unroll
            for (int m = 0; m < 2; m++) {
                #pragma unroll
                for (int ntg = 0; ntg < 2; ntg++) {
                    mma_f16(acc[m][0][ntg * 2 + 0], afr[cur][0],
                            bfr[cur][m][ntg][0], bfr[cur][m][ntg][1]);
                    mma_f16(acc[m][0][ntg * 2 + 1], afr[cur][0],
                            bfr[cur][m][ntg][2], bfr[cur][m][ntg][3]);
                    mma_f16(acc[m][1][ntg * 2 + 0], afr[cur][1],
                            bfr[cur][m][ntg][0], bfr[cur][m][ntg][1]);
                    mma_f16(acc[m][1][ntg * 2 + 1], afr[cur][1],
                            bfr[cur][m][ntg][2], bfr[cur][m][ntg][3]);
                }
            }
        }
    }

    // ---- epilogue: phase mix + bias + ELU ----------------------------------
    #pragma unroll
    for (int mt = 0; mt < 2; mt++) {
        #pragma unroll
        for (int rr = 0; rr < 2; rr++) {
            const size_t r = blockM + warp_m * 32 + mt * 16 + rr * 8 + (lane >> 2);
            const float p0 = __ldg(xphase + r * 258 + 256);
            const float p1 = __ldg(xphase + r * 258 + 257);
            #pragma unroll
            for (int nt = 0; nt < 4; nt++) {
                const int col = blockN + warp_n * 32 + nt * 8 + (lane & 3) * 2;
                float v0 = p0 * acc[0][mt][nt][rr * 2 + 0]
                         + p1 * acc[1][mt][nt][rr * 2 + 0]
                         + p0 * __ldg(bias0 + col) + p1 * __ldg(bias1 + col);
                float v1 = p0 * acc[0][mt][nt][rr * 2 + 1]
                         + p1 * acc[1][mt][nt][rr * 2 + 1]
                         + p0 * __ldg(bias0 + col + 1) + p1 * __ldg(bias1 + col + 1);
                if (DO_ELU) {
                    v0 = v0 > 0.0f ? v0 : expm1f(v0);
                    v1 = v1 > 0.0f ? v1 : expm1f(v1);
                }
                if (OUT_HALF) {
                    __half* C = (__half*)Cv;
                    *reinterpret_cast<__half2*>(C + r * ldc + col) =
                        __floats2half2_rn(v0, v1);
                } else {
                    float* C = (float*)Cv;
                    *reinterpret_cast<float2*>(C + r * ldc + col) =
                        make_float2(v0, v1);
                }
            }
        }
    }
}

// ---------------------------------------------------------------------------
extern "C" void kernel_launch(void* const* d_in, const int* in_sizes, int n_in,
                              void* d_out, int out_size)
{
    const float* x  = (const float*)d_in[0];   // [B, 258]
    const float* w1 = (const float*)d_in[1];   // [2, 256, 1024]
    const float* b1 = (const float*)d_in[2];
    const float* w2 = (const float*)d_in[3];   // [2, 1024, 1024]
    const float* b2 = (const float*)d_in[4];
    const float* w3 = (const float*)d_in[5];   // [2, 1024, 64]
    const float* b3 = (const float*)d_in[6];
    float* out = (float*)d_out;

    const int M = 32768, DIN = 256, H = 1024, DOUT = 64;

    __half *xh, *w1h, *w2h, *w3h, *h1, *h2;
    cudaGetSymbolAddress((void**)&xh,  g_xh);
    cudaGetSymbolAddress((void**)&w1h, g_w1h);
    cudaGetSymbolAddress((void**)&w2h, g_w2h);
    cudaGetSymbolAddress((void**)&w3h, g_w3h);
    cudaGetSymbolAddress((void**)&h1,  g_h1);
    cudaGetSymbolAddress((void**)&h2,  g_h2);

    const int SMEM = 3 * (128 * 128 + 2 * 64 * 128);   // 98304 (3 stages)
    cudaFuncSetAttribute((const void*)hgemm<256, true, true>,
                         cudaFuncAttributeMaxDynamicSharedMemorySize, SMEM);
    cudaFuncSetAttribute((const void*)hgemm<1024, true, true>,
                         cudaFuncAttributeMaxDynamicSharedMemorySize, SMEM);
    cudaFuncSetAttribute((const void*)hgemm<1024, false, false>,
                         cudaFuncAttributeMaxDynamicSharedMemorySize, SMEM);

    // preprocess: convert to half once (2 launches)
    conv_x_kernel<<<M * 128 / 256, 256>>>(x, xh);
    {
        int n1 = 2 * DIN * H / 4, n2 = 2 * H * H / 4, n3 = 2 * H * DOUT / 4;
        conv_w3_kernel<<<(n1 + n2 + n3 + 255) / 256, 256>>>(
            w1, w1h, w2, w2h, w3, w3h, n1, n2, n3);
    }

    dim3 blk(NTHREADS);
    // L1: xh[32768,256] @ w1 -> elu -> h1 (half)
    hgemm<256, true, true><<<dim3(H / TBN, M / TBM), blk, SMEM>>>(
        xh, w1h, (size_t)DIN * H, H, b1, b1 + H, x, h1, H);
    // L2: h1 @ w2 -> elu -> h2 (half)
    hgemm<1024, true, true><<<dim3(H / TBN, M / TBM), blk, SMEM>>>(
        h1, w2h, (size_t)H * H, H, b2, b2 + H, x, h2, H);
    // L3: h2 @ w3 -> out (f32)
    hgemm<1024, false, false><<<dim3(DOUT / TBN, M / TBM), blk, SMEM>>>(
        h2, w3h, (size_t)H * DOUT, DOUT, b3, b3 + DOUT, x, out, DOUT);
}